// round 13
// baseline (speedup 1.0000x reference)
#include <cuda_runtime.h>

#define NB   8
#define CIN  64
#define HID  128
#define HH   192
#define WW   192
#define PIX  (HH*WW)   /* 36864 */

typedef unsigned long long u64;

__device__ __forceinline__ u64 pack2(float lo, float hi) {
    u64 d;
    asm("mov.b64 %0, {%1,%2};" : "=l"(d)
        : "r"(__float_as_uint(lo)), "r"(__float_as_uint(hi)));
    return d;
}
__device__ __forceinline__ void unpack2(u64 v, float& lo, float& hi) {
    unsigned a, b;
    asm("mov.b64 {%0,%1}, %2;" : "=r"(a), "=r"(b) : "l"(v));
    lo = __uint_as_float(a); hi = __uint_as_float(b);
}
__device__ __forceinline__ u64 ffma2(u64 a, u64 b, u64 c) {
    u64 d;
    asm("fma.rn.f32x2 %0, %1, %2, %3;" : "=l"(d) : "l"(a), "l"(b), "l"(c));
    return d;
}
__device__ __forceinline__ unsigned cvt_tf32(float f) {
    unsigned u;
    asm("cvt.rna.tf32.f32 %0, %1;" : "=r"(u) : "f"(f));
    return u;
}
__device__ __forceinline__ void mma_tf32(
    float& d0, float& d1, float& d2, float& d3,
    unsigned a0, unsigned a1, unsigned a2, unsigned a3,
    unsigned b0, unsigned b1) {
    asm("mma.sync.aligned.m16n8k8.row.col.f32.tf32.tf32.f32 "
        "{%0,%1,%2,%3},{%4,%5,%6,%7},{%8,%9},{%0,%1,%2,%3};"
        : "+f"(d0), "+f"(d1), "+f"(d2), "+f"(d3)
        : "r"(a0), "r"(a1), "r"(a2), "r"(a3), "r"(b0), "r"(b1));
}

// scratch (allocation-guard-safe __device__ globals)
__device__ float g_xmean[NB * CIN];
__device__ float g_gg[NB * HID];
__device__ float g_dk[NB * HID * 9];

// ---------------------------------------------------------------------------
// K1: per-(b,c) mean of x (mean(h) = W_in @ mean(x) + b_in by linearity).
// ---------------------------------------------------------------------------
__global__ __launch_bounds__(256) void k_xmean(const float* __restrict__ x) {
    int bc = blockIdx.x;
    const float4* xp = (const float4*)(x + (size_t)bc * PIX);
    float s0 = 0.f, s1 = 0.f, s2 = 0.f, s3 = 0.f;
    int i = threadIdx.x;
    #pragma unroll 1
    for (; i + 768 < PIX / 4; i += 1024) {
        float4 a = xp[i],       bq = xp[i + 256];
        float4 c = xp[i + 512], d  = xp[i + 768];
        s0 += (a.x + a.y) + (a.z + a.w);
        s1 += (bq.x + bq.y) + (bq.z + bq.w);
        s2 += (c.x + c.y) + (c.z + c.w);
        s3 += (d.x + d.y) + (d.z + d.w);
    }
    for (; i < PIX / 4; i += 256) {
        float4 a = xp[i];
        s0 += (a.x + a.y) + (a.z + a.w);
    }
    float s = (s0 + s1) + (s2 + s3);
    __shared__ float red[256];
    red[threadIdx.x] = s;
    __syncthreads();
    for (int off = 128; off > 0; off >>= 1) {
        if (threadIdx.x < off) red[threadIdx.x] += red[threadIdx.x + off];
        __syncthreads();
    }
    if (threadIdx.x == 0) g_xmean[bc] = red[0] * (1.0f / PIX);
}

// ---------------------------------------------------------------------------
// K2a: hmean -> relu(wg1 @ hmean + bg1) = gg. 4 blocks.
// ---------------------------------------------------------------------------
__global__ __launch_bounds__(256) void k_genAB(
    const float* __restrict__ w_in, const float* __restrict__ b_in,
    const float* __restrict__ wg1,  const float* __restrict__ bg1) {
    __shared__ float hm[NB * HID];
    int tid = threadIdx.x;
    for (int idx = tid; idx < NB * HID; idx += 256) {
        int b = idx / HID, o = idx % HID;
        float s = b_in[o];
        #pragma unroll 16
        for (int c = 0; c < CIN; c++) s += w_in[o * CIN + c] * g_xmean[b * CIN + c];
        hm[idx] = s;
    }
    __syncthreads();
    int idx = blockIdx.x * 256 + tid;
    int b = idx / HID, j = idx % HID;
    float s = bg1[j];
    const float4* wr = (const float4*)&wg1[j * HID];
    const float4* hr = (const float4*)&hm[b * HID];
    #pragma unroll 8
    for (int o = 0; o < HID / 4; o++) {
        float4 w = wr[o], h = hr[o];
        s += w.x * h.x + w.y * h.y + w.z * h.z + w.w * h.w;
    }
    g_gg[idx] = s > 0.f ? s : 0.f;
}

// ---------------------------------------------------------------------------
// K2b: dk = wg2 @ gg + bg2. 36 blocks; wg2 staged coalesced; read once.
// ---------------------------------------------------------------------------
__global__ __launch_bounds__(256) void k_genC(
    const float* __restrict__ wg2, const float* __restrict__ bg2) {
    __shared__ float w2s[32 * 128];
    __shared__ float ggs[NB * HID];
    int tid = threadIdx.x;
    int m0 = blockIdx.x * 32;
    for (int idx = tid; idx < 32 * 128 / 4; idx += 256)
        *(float4*)&w2s[idx * 4] = *(const float4*)&wg2[(size_t)m0 * HID + idx * 4];
    for (int idx = tid; idx < NB * HID / 4; idx += 256)
        *(float4*)&ggs[idx * 4] = *(const float4*)&g_gg[idx * 4];
    __syncthreads();
    int ml = tid >> 3, b = tid & 7;
    float s = bg2[m0 + ml];
    #pragma unroll 8
    for (int j = 0; j < HID / 4; j++) {
        float4 w = *(const float4*)&w2s[ml * 128 + j * 4];
        float4 g = *(const float4*)&ggs[b * HID + j * 4];
        s += w.x * g.x + w.y * g.y + w.z * g.z + w.w * g.w;
    }
    g_dk[b * HID * 9 + m0 + ml] = s;
}

// ---------------------------------------------------------------------------
// K3: fused h=W_in@x (tensor-core tf32 3x-split MMA) -> per-sample dw3x3 +
// LeakyReLU -> out=W_out@y + b_out (f32x2). 1024 threads.
// ---------------------------------------------------------------------------
#define XROW 344   /* 34*10=340 used, pitch 344 */
#define YROW 264   /* 256 used */
#define CHK  32

__global__ __launch_bounds__(1024, 1) void k_fused(
    const float* __restrict__ x, const float* __restrict__ w_in,
    const float* __restrict__ b_in, const float* __restrict__ w_out,
    const float* __restrict__ b_out, float* __restrict__ out) {
    extern __shared__ float sm[];
    float* xs   = sm;                     // [64][344]  x halo tile  (22016)
    float* awhi = xs + 64 * XROW;         // [2048] A-frag hi (Mt,k,lane,i)
    float* awlo = awhi + 2048;            // [2048] A-frag lo
    float* bsm  = awlo + 2048;            // [32]   bias chunk
    float* wt   = bsm + 32;               // [128][68]  w_out^T
    float* dks  = wt + 128 * 68;          // [1152]
    float* hsm  = dks + 1152;             // [32][344]
    float* ylc  = hsm + CHK * XROW;       // [32][264]
    // total 55456 floats = 221824 B

    int b   = blockIdx.z;
    int tx0 = blockIdx.x * 32;
    int ty0 = blockIdx.y * 8;
    int tid = threadIdx.x;
    int lane = tid & 31, wrp = tid >> 5;

    // one-time loads
    for (int idx = tid; idx < CIN * HID; idx += 1024) {
        int c = idx >> 6, o = idx & 63;
        wt[c * 68 + o] = w_out[o * HID + c];
    }
    for (int idx = tid; idx < HID * 9; idx += 1024)
        dks[idx] = g_dk[b * HID * 9 + idx];
    for (int idx = tid; idx < 64 * XROW; idx += 1024) {
        int c = idx / XROW, hp = idx - c * XROW;
        float v = 0.f;
        if (hp < 340) {
            int hy = hp / 34, hx = hp - hy * 34;
            int gy = ty0 + hy - 1, gx = tx0 + hx - 1;
            if (gy >= 0 && gy < HH && gx >= 0 && gx < WW)
                v = x[(size_t)(b * CIN + c) * PIX + gy * WW + gx];
        }
        xs[c * XROW + hp] = v;
    }

    // MMA lane decomposition
    int g = lane >> 2, t = lane & 3;

    // out-proj map (R9 proven): ly constant per warp-pair, y distinct
    int lx = tid & 63;          // 4-px strip
    int ly = tid >> 6;          // 0..15, o strip = ly*4

    u64 acc2[2][4];             // 2 o-pairs x 4 px
    #pragma unroll
    for (int i = 0; i < 2; i++)
        #pragma unroll
        for (int j = 0; j < 4; j++) acc2[i][j] = 0ULL;

    for (int cc = 0; cc < HID; cc += CHK) {
        __syncthreads();
        // stage A fragments (w_in chunk, tf32 hi/lo, fragment-ordered)
        for (int pass = 0; pass < 2; pass++) {
            int idx = pass * 1024 + tid;        // 0..2047
            int i  = idx & 3;
            int ln = (idx >> 2) & 31;
            int k  = (idx >> 7) & 7;
            int Mt = idx >> 10;
            int ch  = Mt * 16 + (ln >> 2) + ((i & 1) << 3);
            int cin = k * 8 + (ln & 3) + ((i >> 1) << 2);
            float w = w_in[(cc + ch) * CIN + cin];
            unsigned hi = cvt_tf32(w);
            float lof = w - __uint_as_float(hi);
            awhi[idx] = __uint_as_float(hi);
            awlo[idx] = __uint_as_float(cvt_tf32(lof));
        }
        if (tid < 32) bsm[tid] = b_in[cc + tid];
        __syncthreads();

        // ---- h GEMM via m16n8k8 tf32 MMA, 3x-split ----
        // 86 tiles: Mt = tt&1 (16 ch), Nt = tt>>1 (8 px)
        for (int tt = wrp; tt < 86; tt += 32) {
            int Mt = tt & 1, Nt = tt >> 1;
            int nb = Nt * 8;
            float bi0 = bsm[Mt * 16 + g], bi1 = bsm[Mt * 16 + g + 8];
            float d0 = bi0, d1 = bi0, d2 = bi1, d3 = bi1;
            const float* xb = &xs[t * XROW + nb + g];
            #pragma unroll
            for (int k = 0; k < 8; k++) {
                float4 ahv = *(const float4*)&awhi[((Mt * 8 + k) * 32 + lane) * 4];
                float4 alv = *(const float4*)&awlo[((Mt * 8 + k) * 32 + lane) * 4];
                float b0f = xb[(k * 8) * XROW];
                float b1f = xb[(k * 8 + 4) * XROW];
                unsigned bh0 = cvt_tf32(b0f), bh1 = cvt_tf32(b1f);
                float bl0f = b0f - __uint_as_float(bh0);
                float bl1f = b1f - __uint_as_float(bh1);
                unsigned bl0 = cvt_tf32(bl0f), bl1 = cvt_tf32(bl1f);
                unsigned a0 = __float_as_uint(ahv.x), a1 = __float_as_uint(ahv.y);
                unsigned a2 = __float_as_uint(ahv.z), a3 = __float_as_uint(ahv.w);
                mma_tf32(d0, d1, d2, d3, a0, a1, a2, a3, bh0, bh1);
                mma_tf32(d0, d1, d2, d3, a0, a1, a2, a3, bl0, bl1);
                unsigned c0 = __float_as_uint(alv.x), c1 = __float_as_uint(alv.y);
                unsigned c2 = __float_as_uint(alv.z), c3 = __float_as_uint(alv.w);
                mma_tf32(d0, d1, d2, d3, c0, c1, c2, c3, bh0, bh1);
            }
            *(float2*)&hsm[(Mt * 16 + g) * XROW + nb + 2 * t]     = make_float2(d0, d1);
            *(float2*)&hsm[(Mt * 16 + g + 8) * XROW + nb + 2 * t] = make_float2(d2, d3);
        }
        __syncthreads();

        // ---- depthwise 3x3 + LeakyReLU: warp-per-channel, rotating taps ----
        {
            int c = wrp;
            float kr[9];
            #pragma unroll
            for (int j = 0; j < 9; j++) kr[j] = dks[(cc + c) * 9 + j];
            const float* hc = &hsm[c * XROW];
            float l0 = hc[lane],      c0 = hc[lane + 1],      r0 = hc[lane + 2];
            float l1 = hc[34 + lane], c1 = hc[34 + lane + 1], r1 = hc[34 + lane + 2];
            #pragma unroll
            for (int i = 0; i < 8; i++) {
                int rb = (i + 2) * 34 + lane;
                float l2 = hc[rb], c2 = hc[rb + 1], r2 = hc[rb + 2];
                float y = kr[0] * l0 + kr[1] * c0 + kr[2] * r0
                        + kr[3] * l1 + kr[4] * c1 + kr[5] * r1
                        + kr[6] * l2 + kr[7] * c2 + kr[8] * r2;
                ylc[c * YROW + i * 32 + lane] = y > 0.f ? y : 0.1f * y;
                l0 = l1; c0 = c1; r0 = r1;
                l1 = l2; c1 = c2; r1 = r2;
            }
        }
        __syncthreads();

        // ---- out-projection accumulate, f32x2 (2 o-pairs x 4 px) ----
        #pragma unroll 4
        for (int c = 0; c < CHK; c++) {
            float4 y = *(const float4*)&ylc[c * YROW + lx * 4];
            u64 yd0 = pack2(y.x, y.x), yd1 = pack2(y.y, y.y);
            u64 yd2 = pack2(y.z, y.z), yd3 = pack2(y.w, y.w);
            ulonglong2 wp = *(const ulonglong2*)&wt[(cc + c) * 68 + ly * 4];
            acc2[0][0] = ffma2(wp.x, yd0, acc2[0][0]);
            acc2[0][1] = ffma2(wp.x, yd1, acc2[0][1]);
            acc2[0][2] = ffma2(wp.x, yd2, acc2[0][2]);
            acc2[0][3] = ffma2(wp.x, yd3, acc2[0][3]);
            acc2[1][0] = ffma2(wp.y, yd0, acc2[1][0]);
            acc2[1][1] = ffma2(wp.y, yd1, acc2[1][1]);
            acc2[1][2] = ffma2(wp.y, yd2, acc2[1][2]);
            acc2[1][3] = ffma2(wp.y, yd3, acc2[1][3]);
        }
    }

    // unpack + write out (+b_out): 4 o x 4 px (R9 direct-store form)
    float vals[4][4];
    #pragma unroll
    for (int op = 0; op < 2; op++)
        #pragma unroll
        for (int j = 0; j < 4; j++)
            unpack2(acc2[op][j], vals[op * 2][j], vals[op * 2 + 1][j]);

    int pxo = lx * 4;
    int py = pxo >> 5, pxx = pxo & 31;
    #pragma unroll
    for (int i = 0; i < 4; i++) {
        int o = ly * 4 + i;
        float bo = __ldg(&b_out[o]);
        size_t base = (size_t)(b * CIN + o) * PIX + (ty0 + py) * WW + tx0 + pxx;
        *(float4*)&out[base] = make_float4(vals[i][0] + bo, vals[i][1] + bo,
                                           vals[i][2] + bo, vals[i][3] + bo);
    }
}

// ---------------------------------------------------------------------------
extern "C" void kernel_launch(void* const* d_in, const int* in_sizes, int n_in,
                              void* d_out, int out_size) {
    const float* x     = (const float*)d_in[0];
    const float* w_in  = (const float*)d_in[1];
    const float* b_in  = (const float*)d_in[2];
    const float* wg1   = (const float*)d_in[3];
    const float* bg1   = (const float*)d_in[4];
    const float* wg2   = (const float*)d_in[5];
    const float* bg2   = (const float*)d_in[6];
    const float* w_out = (const float*)d_in[7];
    const float* b_out = (const float*)d_in[8];
    float* out = (float*)d_out;

    k_xmean<<<NB * CIN, 256>>>(x);
    k_genAB<<<4, 256>>>(w_in, b_in, wg1, bg1);
    k_genC<<<36, 256>>>(wg2, bg2);

    int smem = 55456 * 4;   // 221824 B
    cudaFuncSetAttribute(k_fused, cudaFuncAttributeMaxDynamicSharedMemorySize, smem);
    k_fused<<<dim3(WW / 32, HH / 8, NB), 1024, smem>>>(
        x, w_in, b_in, w_out, b_out, out);
}

// round 14
// speedup vs baseline: 1.7976x; 1.7976x over previous
#include <cuda_runtime.h>

#define NB   8
#define CIN  64
#define HID  128
#define HH   192
#define WW   192
#define PIX  (HH*WW)   /* 36864 */

typedef unsigned long long u64;

__device__ __forceinline__ u64 pack2(float lo, float hi) {
    u64 d;
    asm("mov.b64 %0, {%1,%2};" : "=l"(d)
        : "r"(__float_as_uint(lo)), "r"(__float_as_uint(hi)));
    return d;
}
__device__ __forceinline__ void unpack2(u64 v, float& lo, float& hi) {
    unsigned a, b;
    asm("mov.b64 {%0,%1}, %2;" : "=r"(a), "=r"(b) : "l"(v));
    lo = __uint_as_float(a); hi = __uint_as_float(b);
}
__device__ __forceinline__ u64 ffma2(u64 a, u64 b, u64 c) {
    u64 d;
    asm("fma.rn.f32x2 %0, %1, %2, %3;" : "=l"(d) : "l"(a), "l"(b), "l"(c));
    return d;
}

// scratch (allocation-guard-safe __device__ globals)
__device__ float g_xmean[NB * CIN];
__device__ float g_gg[NB * HID];
__device__ float g_dk[NB * HID * 9];
__device__ float g_h[(size_t)NB * HID * PIX];   // 151 MB intermediate

// ---------------------------------------------------------------------------
// K1: per-(b,c) mean of x (mean(h) = W_in @ mean(x) + b_in by linearity).
// ---------------------------------------------------------------------------
__global__ __launch_bounds__(256) void k_xmean(const float* __restrict__ x) {
    int bc = blockIdx.x;
    const float4* xp = (const float4*)(x + (size_t)bc * PIX);
    float s0 = 0.f, s1 = 0.f, s2 = 0.f, s3 = 0.f;
    int i = threadIdx.x;
    #pragma unroll 1
    for (; i + 768 < PIX / 4; i += 1024) {
        float4 a = xp[i],       bq = xp[i + 256];
        float4 c = xp[i + 512], d  = xp[i + 768];
        s0 += (a.x + a.y) + (a.z + a.w);
        s1 += (bq.x + bq.y) + (bq.z + bq.w);
        s2 += (c.x + c.y) + (c.z + c.w);
        s3 += (d.x + d.y) + (d.z + d.w);
    }
    for (; i < PIX / 4; i += 256) {
        float4 a = xp[i];
        s0 += (a.x + a.y) + (a.z + a.w);
    }
    float s = (s0 + s1) + (s2 + s3);
    __shared__ float red[256];
    red[threadIdx.x] = s;
    __syncthreads();
    for (int off = 128; off > 0; off >>= 1) {
        if (threadIdx.x < off) red[threadIdx.x] += red[threadIdx.x + off];
        __syncthreads();
    }
    if (threadIdx.x == 0) g_xmean[bc] = red[0] * (1.0f / PIX);
}

// ---------------------------------------------------------------------------
// K2a: hmean -> relu(wg1 @ hmean + bg1) = gg. 4 blocks.
// ---------------------------------------------------------------------------
__global__ __launch_bounds__(256) void k_genAB(
    const float* __restrict__ w_in, const float* __restrict__ b_in,
    const float* __restrict__ wg1,  const float* __restrict__ bg1) {
    __shared__ float hm[NB * HID];
    int tid = threadIdx.x;
    for (int idx = tid; idx < NB * HID; idx += 256) {
        int b = idx / HID, o = idx % HID;
        float s = b_in[o];
        #pragma unroll 16
        for (int c = 0; c < CIN; c++) s += w_in[o * CIN + c] * g_xmean[b * CIN + c];
        hm[idx] = s;
    }
    __syncthreads();
    int idx = blockIdx.x * 256 + tid;
    int b = idx / HID, j = idx % HID;
    float s = bg1[j];
    const float4* wr = (const float4*)&wg1[j * HID];
    const float4* hr = (const float4*)&hm[b * HID];
    #pragma unroll 8
    for (int o = 0; o < HID / 4; o++) {
        float4 w = wr[o], h = hr[o];
        s += w.x * h.x + w.y * h.y + w.z * h.z + w.w * h.w;
    }
    g_gg[idx] = s > 0.f ? s : 0.f;
}

// ---------------------------------------------------------------------------
// K2b: dk = wg2 @ gg + bg2. 36 blocks; wg2 staged coalesced; read once.
// ---------------------------------------------------------------------------
__global__ __launch_bounds__(256) void k_genC(
    const float* __restrict__ wg2, const float* __restrict__ bg2) {
    __shared__ float w2s[32 * 128];
    __shared__ float ggs[NB * HID];
    int tid = threadIdx.x;
    int m0 = blockIdx.x * 32;
    for (int idx = tid; idx < 32 * 128 / 4; idx += 256)
        *(float4*)&w2s[idx * 4] = *(const float4*)&wg2[(size_t)m0 * HID + idx * 4];
    for (int idx = tid; idx < NB * HID / 4; idx += 256)
        *(float4*)&ggs[idx * 4] = *(const float4*)&g_gg[idx * 4];
    __syncthreads();
    int ml = tid >> 3, b = tid & 7;
    float s = bg2[m0 + ml];
    #pragma unroll 8
    for (int j = 0; j < HID / 4; j++) {
        float4 w = *(const float4*)&w2s[ml * 128 + j * 4];
        float4 g = *(const float4*)&ggs[b * HID + j * 4];
        s += w.x * g.x + w.y * g.y + w.z * g.z + w.w * g.w;
    }
    g_dk[b * HID * 9 + m0 + ml] = s;
}

// ---------------------------------------------------------------------------
// K3: h = W_in @ x + b_in. Pure SGEMM, one barrier, f32x2 (ch-pairs from
// pre-transposed smem weights -> zero packs on W). 1024 thr, 8ch x 4px/thread.
// ---------------------------------------------------------------------------
__global__ __launch_bounds__(1024, 1) void k_proj(
    const float* __restrict__ x, const float* __restrict__ w_in,
    const float* __restrict__ b_in) {
    extern __shared__ float sp[];
    float* xs  = sp;             // [64][256]
    float* wsT = sp + 64 * 256;  // [64][132]  w_in^T, [cin][hid]
    int b  = blockIdx.y;
    int p0 = blockIdx.x * 256;
    int tid = threadIdx.x;

    for (int idx = tid; idx < CIN * HID; idx += 1024) {
        int ch = idx & 127, c = idx >> 7;
        wsT[c * 132 + ch] = w_in[ch * CIN + c];
    }
    for (int idx = tid; idx < 64 * 64; idx += 1024) {
        int c = idx >> 6, pg = (idx & 63) << 2;
        *(float4*)&xs[c * 256 + pg] =
            *(const float4*)&x[(size_t)(b * CIN + c) * PIX + p0 + pg];
    }
    __syncthreads();

    int och = (tid >> 6) * 8;   // warp-uniform
    int pxg = tid & 63;

    u64 acc2[4][4];
    #pragma unroll
    for (int i = 0; i < 4; i++)
        #pragma unroll
        for (int j = 0; j < 4; j++) acc2[i][j] = 0ULL;

    #pragma unroll 8
    for (int c = 0; c < CIN; c++) {
        float4 xv = *(const float4*)&xs[c * 256 + pxg * 4];
        u64 yd0 = pack2(xv.x, xv.x), yd1 = pack2(xv.y, xv.y);
        u64 yd2 = pack2(xv.z, xv.z), yd3 = pack2(xv.w, xv.w);
        ulonglong2 wa = *(const ulonglong2*)&wsT[c * 132 + och];
        ulonglong2 wb = *(const ulonglong2*)&wsT[c * 132 + och + 4];
        acc2[0][0] = ffma2(wa.x, yd0, acc2[0][0]);
        acc2[0][1] = ffma2(wa.x, yd1, acc2[0][1]);
        acc2[0][2] = ffma2(wa.x, yd2, acc2[0][2]);
        acc2[0][3] = ffma2(wa.x, yd3, acc2[0][3]);
        acc2[1][0] = ffma2(wa.y, yd0, acc2[1][0]);
        acc2[1][1] = ffma2(wa.y, yd1, acc2[1][1]);
        acc2[1][2] = ffma2(wa.y, yd2, acc2[1][2]);
        acc2[1][3] = ffma2(wa.y, yd3, acc2[1][3]);
        acc2[2][0] = ffma2(wb.x, yd0, acc2[2][0]);
        acc2[2][1] = ffma2(wb.x, yd1, acc2[2][1]);
        acc2[2][2] = ffma2(wb.x, yd2, acc2[2][2]);
        acc2[2][3] = ffma2(wb.x, yd3, acc2[2][3]);
        acc2[3][0] = ffma2(wb.y, yd0, acc2[3][0]);
        acc2[3][1] = ffma2(wb.y, yd1, acc2[3][1]);
        acc2[3][2] = ffma2(wb.y, yd2, acc2[3][2]);
        acc2[3][3] = ffma2(wb.y, yd3, acc2[3][3]);
    }

    float vals[8][4];
    #pragma unroll
    for (int p = 0; p < 4; p++)
        #pragma unroll
        for (int j = 0; j < 4; j++)
            unpack2(acc2[p][j], vals[2 * p][j], vals[2 * p + 1][j]);

    #pragma unroll
    for (int i = 0; i < 8; i++) {
        float bo = __ldg(&b_in[och + i]);
        *(float4*)&g_h[(size_t)(b * HID + och + i) * PIX + p0 + pxg * 4] =
            make_float4(vals[i][0] + bo, vals[i][1] + bo,
                        vals[i][2] + bo, vals[i][3] + bo);
    }
}

// ---------------------------------------------------------------------------
// K4: per-sample dw3x3 + LeakyReLU + out = W_out@y + b_out.
// 512 thr, 2 blocks/SM (smem 112640B, regs<=64). h halo chunk from g_h.
// ---------------------------------------------------------------------------
#define XROW 344   /* 34*10=340 used */
#define YROW 264   /* 256 used */
#define CHK  32

__global__ __launch_bounds__(512, 2) void k_dwout(
    const float* __restrict__ w_out, const float* __restrict__ b_out,
    float* __restrict__ out) {
    extern __shared__ float sd[];
    float* hsm = sd;                   // [32][344]
    float* ylc = hsm + CHK * XROW;     // [32][264]
    float* wt  = ylc + CHK * YROW;     // [128][68]  w_out^T
    // total (11008+8448+8704)*4 = 112640 B

    int b   = blockIdx.z;
    int tx0 = blockIdx.x * 32;
    int ty0 = blockIdx.y * 8;
    int tid = threadIdx.x;
    int lane = tid & 31, wrp = tid >> 5;

    for (int idx = tid; idx < CIN * HID; idx += 512) {
        int o = idx & 63, c = idx >> 6;
        wt[c * 68 + o] = w_out[o * HID + c];
    }

    int och = (tid >> 6) * 8;   // warp-uniform (8 groups x 8 out-ch)
    int pxg = tid & 63;

    u64 acc2[4][4];
    #pragma unroll
    for (int i = 0; i < 4; i++)
        #pragma unroll
        for (int j = 0; j < 4; j++) acc2[i][j] = 0ULL;

    for (int cc = 0; cc < HID; cc += CHK) {
        __syncthreads();
        // stage h halo chunk (zero-padded SAME)
        for (int idx = tid; idx < CHK * 340; idx += 512) {
            int c = idx / 340, hp = idx - c * 340;
            int hy = hp / 34,  hx = hp - hy * 34;
            int gy = ty0 + hy - 1, gx = tx0 + hx - 1;
            float v = 0.f;
            if (gy >= 0 && gy < HH && gx >= 0 && gx < WW)
                v = g_h[(size_t)(b * HID + cc + c) * PIX + gy * WW + gx];
            hsm[c * XROW + hp] = v;
        }
        __syncthreads();

        // ---- depthwise 3x3 + LeakyReLU: 16 warps x 2ch, rotating taps ----
        #pragma unroll
        for (int ii = 0; ii < 2; ii++) {
            int c = wrp * 2 + ii;
            float kr[9];
            #pragma unroll
            for (int j = 0; j < 9; j++)
                kr[j] = __ldg(&g_dk[(b * HID + cc + c) * 9 + j]);
            const float* hc = &hsm[c * XROW];
            float l0 = hc[lane],      c0 = hc[lane + 1],      r0 = hc[lane + 2];
            float l1 = hc[34 + lane], c1 = hc[34 + lane + 1], r1 = hc[34 + lane + 2];
            #pragma unroll
            for (int i = 0; i < 8; i++) {
                int rb = (i + 2) * 34 + lane;
                float l2 = hc[rb], c2 = hc[rb + 1], r2 = hc[rb + 2];
                float y = kr[0] * l0 + kr[1] * c0 + kr[2] * r0
                        + kr[3] * l1 + kr[4] * c1 + kr[5] * r1
                        + kr[6] * l2 + kr[7] * c2 + kr[8] * r2;
                ylc[c * YROW + i * 32 + lane] = y > 0.f ? y : 0.1f * y;
                l0 = l1; c0 = c1; r0 = r1;
                l1 = l2; c1 = c2; r1 = r2;
            }
        }
        __syncthreads();

        // ---- out-projection accumulate: 8ch x 4px, f32x2 ch-pairs ----
        #pragma unroll 4
        for (int c = 0; c < CHK; c++) {
            float4 y = *(const float4*)&ylc[c * YROW + pxg * 4];
            u64 yd0 = pack2(y.x, y.x), yd1 = pack2(y.y, y.y);
            u64 yd2 = pack2(y.z, y.z), yd3 = pack2(y.w, y.w);
            ulonglong2 wa = *(const ulonglong2*)&wt[(cc + c) * 68 + och];
            ulonglong2 wb = *(const ulonglong2*)&wt[(cc + c) * 68 + och + 4];
            acc2[0][0] = ffma2(wa.x, yd0, acc2[0][0]);
            acc2[0][1] = ffma2(wa.x, yd1, acc2[0][1]);
            acc2[0][2] = ffma2(wa.x, yd2, acc2[0][2]);
            acc2[0][3] = ffma2(wa.x, yd3, acc2[0][3]);
            acc2[1][0] = ffma2(wa.y, yd0, acc2[1][0]);
            acc2[1][1] = ffma2(wa.y, yd1, acc2[1][1]);
            acc2[1][2] = ffma2(wa.y, yd2, acc2[1][2]);
            acc2[1][3] = ffma2(wa.y, yd3, acc2[1][3]);
            acc2[2][0] = ffma2(wb.x, yd0, acc2[2][0]);
            acc2[2][1] = ffma2(wb.x, yd1, acc2[2][1]);
            acc2[2][2] = ffma2(wb.x, yd2, acc2[2][2]);
            acc2[2][3] = ffma2(wb.x, yd3, acc2[2][3]);
            acc2[3][0] = ffma2(wb.y, yd0, acc2[3][0]);
            acc2[3][1] = ffma2(wb.y, yd1, acc2[3][1]);
            acc2[3][2] = ffma2(wb.y, yd2, acc2[3][2]);
            acc2[3][3] = ffma2(wb.y, yd3, acc2[3][3]);
        }
    }

    // unpack + write out (+b_out): 8 ch x 4 px, coalesced
    float vals[8][4];
    #pragma unroll
    for (int p = 0; p < 4; p++)
        #pragma unroll
        for (int j = 0; j < 4; j++)
            unpack2(acc2[p][j], vals[2 * p][j], vals[2 * p + 1][j]);

    int pxo = pxg * 4;
    int py = pxo >> 5, pxx = pxo & 31;
    #pragma unroll
    for (int i = 0; i < 8; i++) {
        int o = och + i;
        float bo = __ldg(&b_out[o]);
        size_t base = (size_t)(b * CIN + o) * PIX + (ty0 + py) * WW + tx0 + pxx;
        *(float4*)&out[base] = make_float4(vals[i][0] + bo, vals[i][1] + bo,
                                           vals[i][2] + bo, vals[i][3] + bo);
    }
}

// ---------------------------------------------------------------------------
extern "C" void kernel_launch(void* const* d_in, const int* in_sizes, int n_in,
                              void* d_out, int out_size) {
    const float* x     = (const float*)d_in[0];
    const float* w_in  = (const float*)d_in[1];
    const float* b_in  = (const float*)d_in[2];
    const float* wg1   = (const float*)d_in[3];
    const float* bg1   = (const float*)d_in[4];
    const float* wg2   = (const float*)d_in[5];
    const float* bg2   = (const float*)d_in[6];
    const float* w_out = (const float*)d_in[7];
    const float* b_out = (const float*)d_in[8];
    float* out = (float*)d_out;

    k_xmean<<<NB * CIN, 256>>>(x);
    k_genAB<<<4, 256>>>(w_in, b_in, wg1, bg1);
    k_genC<<<36, 256>>>(wg2, bg2);

    int smem_p = (64 * 256 + 64 * 132) * 4;   // 99328 B
    cudaFuncSetAttribute(k_proj, cudaFuncAttributeMaxDynamicSharedMemorySize, smem_p);
    k_proj<<<dim3(PIX / 256, NB), 1024, smem_p>>>(x, w_in, b_in);

    int smem_d = (CHK * XROW + CHK * YROW + 128 * 68) * 4;   // 112640 B
    cudaFuncSetAttribute(k_dwout, cudaFuncAttributeMaxDynamicSharedMemorySize, smem_d);
    k_dwout<<<dim3(WW / 32, HH / 8, NB), 512, smem_d>>>(w_out, b_out, out);
}